// round 5
// baseline (speedup 1.0000x reference)
#include <cuda_runtime.h>
#include <cuda_fp16.h>
#include <cstdint>

#define Bb 32
#define Ss 512
#define Dd 1024
#define Hh 1024
#define Mm (Bb*Ss)     // 16384, row order m' = s*32 + b
#define Nn 4096        // 4 gates * H, n = 4*h + g  (g: 0=f,1=i,2=l,3=u)
#define Kk 1024

// ---- scratch (device globals) ----
__device__ __half g_A[(size_t)Mm*Kk];     // fp16 inp, rows m' = s*32+b
__device__ __half g_W[(size_t)Kk*Nn];     // fp16 packed weights [k][4h+g]
__device__ __half g_Gt[(size_t)Mm*Nn];    // gates (no hv), layout ((h*512+s)*32+b)*4+g
__device__ float  g_hvT[1024*128];        // hvT[h][b*4+g]
__device__ float  g_hvp[8*32*4096];       // k-split partials [ks][b][g*1024+h]

// ================= convert / pack =================
__global__ void conv_inp_kernel(const float* __restrict__ inp){
    size_t i = (size_t)blockIdx.x*blockDim.x + threadIdx.x;   // float4 index
    int row = (int)(i >> 8);                 // 256 float4 per 1024-col row
    int cb  = (int)(i & 255);
    int b = row >> 9, s = row & 511;
    int nrow = s*32 + b;
    float4 v = ((const float4*)inp)[i];
    __half2* dst = (__half2*)(g_A + (size_t)nrow*1024 + cb*4);
    dst[0] = __floats2half2_rn(v.x, v.y);
    dst[1] = __floats2half2_rn(v.z, v.w);
}

__global__ void pack_w_kernel(const float* __restrict__ Uf, const float* __restrict__ Ui,
                              const float* __restrict__ Ul, const float* __restrict__ Uu){
    int idx = blockIdx.x*blockDim.x + threadIdx.x;  // k*1024 + h
    int k = idx >> 10, h = idx & 1023;
    __half2 p0 = __floats2half2_rn(Uf[idx], Ui[idx]);
    __half2 p1 = __floats2half2_rn(Ul[idx], Uu[idx]);
    __half2* dst = (__half2*)(g_W + (size_t)k*Nn + 4*h);
    dst[0] = p0; dst[1] = p1;
}

// ================= hv: k-split partial GEMV =================
__global__ __launch_bounds__(256) void hv_part_kernel(const float* __restrict__ h0,
                          const float* __restrict__ Vf, const float* __restrict__ Vi,
                          const float* __restrict__ Vl, const float* __restrict__ Vu){
    const int ks = blockIdx.x & 7;
    const int gh = blockIdx.x >> 3;
    const int g  = gh >> 2, hc = gh & 3;
    const float* V = (g==0)?Vf:(g==1)?Vi:(g==2)?Vl:Vu;
    const int t = threadIdx.x;
    const int k0 = ks*128;
    __shared__ float s0[32][128];
    #pragma unroll
    for (int i = 0; i < 16; ++i){
        int idx = t + i*256;
        s0[idx >> 7][idx & 127] = h0[(idx >> 7)*1024 + k0 + (idx & 127)];
    }
    __syncthreads();
    const int h = hc*256 + t;
    float acc[32];
    #pragma unroll
    for (int b = 0; b < 32; ++b) acc[b] = 0.f;
    for (int k = 0; k < 128; ++k){
        float v = V[(size_t)(k0 + k)*1024 + h];
        #pragma unroll
        for (int b = 0; b < 32; ++b) acc[b] = fmaf(s0[b][k], v, acc[b]);
    }
    #pragma unroll
    for (int b = 0; b < 32; ++b)
        g_hvp[((size_t)ks*32 + b)*4096 + g*1024 + h] = acc[b];
}

__global__ __launch_bounds__(256) void hv_reduce_kernel(const float* __restrict__ Bf,
                          const float* __restrict__ Bi, const float* __restrict__ Bl,
                          const float* __restrict__ Bu){
    int idx = blockIdx.x*256 + threadIdx.x;   // 0..32767
    int b = idx >> 10, h = idx & 1023;
    float s0 = Bf[h], s1 = Bi[h], s2 = Bl[h], s3 = Bu[h];
    #pragma unroll
    for (int ks = 0; ks < 8; ++ks){
        const float* p = g_hvp + ((size_t)ks*32 + b)*4096;
        s0 += p[h]; s1 += p[1024 + h]; s2 += p[2048 + h]; s3 += p[3072 + h];
    }
    ((float4*)g_hvT)[h*32 + b] = make_float4(s0, s1, s2, s3);
}

// ================= GEMM: fp16 mma.sync, 4 warps, warp tile 64x64 =================
#define BM 128
#define BN 128
#define BKk 64
#define APAD 72                 // halfs per A row
#define BPAD 136                // halfs per B row
#define ABYTES (BM*APAD*2)      // 18432
#define BBYTES (BKk*BPAD*2)     // 17408
#define NSTAGE 3
#define GEMM_SMEM (NSTAGE*(ABYTES+BBYTES))   // 107520
#define NPITCH 132              // epilogue fp32 tile pitch (floats)

__device__ __forceinline__ void cp16(uint32_t d, const void* s){
    asm volatile("cp.async.cg.shared.global [%0], [%1], 16;" :: "r"(d), "l"(s));
}
#define CP_COMMIT() asm volatile("cp.async.commit_group;")
#define CP_WAIT(n)  asm volatile("cp.async.wait_group %0;" :: "n"(n))

__device__ __forceinline__ void ldsm_x4(uint32_t& r0,uint32_t& r1,uint32_t& r2,uint32_t& r3,uint32_t a){
    asm volatile("ldmatrix.sync.aligned.m8n8.x4.shared.b16 {%0,%1,%2,%3},[%4];"
        : "=r"(r0),"=r"(r1),"=r"(r2),"=r"(r3) : "r"(a));
}
__device__ __forceinline__ void ldsm_x4t(uint32_t& r0,uint32_t& r1,uint32_t& r2,uint32_t& r3,uint32_t a){
    asm volatile("ldmatrix.sync.aligned.m8n8.x4.trans.shared.b16 {%0,%1,%2,%3},[%4];"
        : "=r"(r0),"=r"(r1),"=r"(r2),"=r"(r3) : "r"(a));
}
__device__ __forceinline__ void mma16816(float* c, const uint32_t* a, const uint32_t* b){
    asm volatile("mma.sync.aligned.m16n8k16.row.col.f32.f16.f16.f32 "
        "{%0,%1,%2,%3},{%4,%5,%6,%7},{%8,%9},{%0,%1,%2,%3};"
        : "+f"(c[0]),"+f"(c[1]),"+f"(c[2]),"+f"(c[3])
        : "r"(a[0]),"r"(a[1]),"r"(a[2]),"r"(a[3]),"r"(b[0]),"r"(b[1]));
}
__device__ __forceinline__ uint32_t smem_u32(const void* p){
    uint32_t a;
    asm("{ .reg .u64 t; cvta.to.shared.u64 t, %1; cvt.u32.u64 %0, t; }" : "=r"(a) : "l"(p));
    return a;
}

__global__ __launch_bounds__(128,2) void gemm_kernel(){
    extern __shared__ __align__(16) char smem[];
    const uint32_t sA = smem_u32(smem);
    const uint32_t sB = sA + NSTAGE*ABYTES;
    const int tid = threadIdx.x;
    const int lane = tid & 31, warp = tid >> 5;
    const int wm = warp >> 1, wn = warp & 1;          // 2(m) x 2(n); warp tile 64x64
    const int m0 = blockIdx.y * BM, n0 = blockIdx.x * BN;

    float acc[4][8][4];
    #pragma unroll
    for (int i=0;i<4;i++)
        #pragma unroll
        for (int j=0;j<8;j++)
            #pragma unroll
            for (int r=0;r<4;r++) acc[i][j][r]=0.f;

    const __half* Ag = g_A + (size_t)m0*Kk;
    const __half* Wg = g_W + n0;

    auto issue = [&](int st, int buf){
        const int k0 = st*BKk;
        #pragma unroll
        for (int i = 0; i < 8; ++i){          // A: 128r x 64c, 1024 chunks
            int idx = tid + i*128;
            int row = idx >> 3, c = idx & 7;
            cp16(sA + buf*ABYTES + (row*APAD + c*8)*2,
                 Ag + (size_t)row*Kk + k0 + c*8);
        }
        #pragma unroll
        for (int i = 0; i < 8; ++i){          // B: 64r x 128c, 1024 chunks
            int idx = tid + i*128;
            int row = idx >> 4, c = idx & 15;
            cp16(sB + buf*BBYTES + (row*BPAD + c*8)*2,
                 Wg + (size_t)(k0 + row)*Nn + c*8);
        }
    };

    auto compute = [&](int buf){
        #pragma unroll
        for (int kk = 0; kk < 4; ++kk){
            uint32_t a[4][4];
            const int arow = wm*64 + (lane & 15);
            const int acol = kk*16 + (lane >> 4)*8;
            #pragma unroll
            for (int mt=0; mt<4; mt++){
                uint32_t ad = sA + buf*ABYTES + (((arow + mt*16)*APAD) + acol)*2;
                ldsm_x4(a[mt][0],a[mt][1],a[mt][2],a[mt][3], ad);
            }
            uint32_t bfr[8][2];
            const int brow = kk*16 + (lane & 15);
            #pragma unroll
            for (int np=0; np<4; np++){
                const int bcol = wn*64 + np*16 + (lane >> 4)*8;
                uint32_t bd = sB + buf*BBYTES + (brow*BPAD + bcol)*2;
                uint32_t r0,r1,r2,r3;
                ldsm_x4t(r0,r1,r2,r3, bd);
                bfr[2*np][0]=r0;   bfr[2*np][1]=r1;
                bfr[2*np+1][0]=r2; bfr[2*np+1][1]=r3;
            }
            #pragma unroll
            for (int mt=0; mt<4; mt++)
                #pragma unroll
                for (int nt=0; nt<8; nt++)
                    mma16816(acc[mt][nt], a[mt], bfr[nt]);
        }
    };

    issue(0,0); CP_COMMIT();
    issue(1,1); CP_COMMIT();

    const int NKT = Kk / BKk;   // 16
    int buf = 0;
    for (int kt = 0; kt < NKT-2; ++kt){
        CP_WAIT(1);
        __syncthreads();
        int wbuf = buf + 2; if (wbuf >= 3) wbuf -= 3;
        issue(kt+2, wbuf); CP_COMMIT();
        compute(buf);
        if (++buf == 3) buf = 0;
    }
    CP_WAIT(1); __syncthreads(); compute(buf); if (++buf == 3) buf = 0;
    CP_WAIT(0); __syncthreads(); compute(buf);

    // ---- epilogue: smem transpose -> g_Gt[h][s][b][g] fp16 (no hv) ----
    __syncthreads();
    float* sT = (float*)smem;   // 128 x NPITCH
    #pragma unroll
    for (int mt=0; mt<4; mt++){
        #pragma unroll
        for (int nt=0; nt<8; nt++){
            const int row = wm*64 + mt*16 + (lane >> 2);
            const int col = wn*64 + nt*8 + (lane & 3)*2;
            *(float2*)&sT[row*NPITCH + col]     = make_float2(acc[mt][nt][0], acc[mt][nt][1]);
            *(float2*)&sT[(row+8)*NPITCH + col] = make_float2(acc[mt][nt][2], acc[mt][nt][3]);
        }
    }
    __syncthreads();

    const int hbase = n0 >> 2;        // 32 h per CTA
    const int s0 = m0 >> 5;           // 4 s per CTA (m' = s*32+b)
    const int sl = lane >> 3, c = lane & 7;
    #pragma unroll
    for (int hb = 0; hb < 8; ++hb){
        const int hl = hb*4 + warp;
        const int hglob = hbase + hl;
        const int s = s0 + sl;
        uint32_t pk[8];
        #pragma unroll
        for (int db = 0; db < 4; ++db){
            const int b = 4*c + db;
            float4 v  = *(const float4*)&sT[(sl*32 + b)*NPITCH + hl*4];
            __half2 lo = __floats2half2_rn(v.x, v.y);
            __half2 hi = __floats2half2_rn(v.z, v.w);
            pk[db*2]   = *(uint32_t*)&lo;
            pk[db*2+1] = *(uint32_t*)&hi;
        }
        char* dst = (char*)g_Gt + ((size_t)(hglob*512 + s)*256) + c*32;
        *(uint4*)dst       = make_uint4(pk[0], pk[1], pk[2], pk[3]);
        *(uint4*)(dst+16)  = make_uint4(pk[4], pk[5], pk[6], pk[7]);
    }
}

// ================= phase 2: hv-add + activations + cumprod =================
__device__ __forceinline__ float sigm(float x){
    return __fdividef(1.f, 1.f + __expf(-x));
}
__device__ __forceinline__ float tanh_f(float x){
    float ax = fabsf(x);
    float e = __expf(-2.f*ax);
    float t = __fdividef(1.f - e, 1.f + e);
    return copysignf(t, x);
}

// grid 256, block 128: warp = one h, lanes = b
__global__ __launch_bounds__(128) void phase2_kernel(const float* __restrict__ c0,
                                                     float* __restrict__ out){
    const int t = threadIdx.x;
    const int w = t >> 5, b = t & 31;
    const int h = blockIdx.x*4 + w;
    float c = c0[b*Hh + h];
    float4 hv = ((const float4*)g_hvT)[h*32 + b];   // (F, I, N, O) biases
    const uint2* gp = (const uint2*)g_Gt + (size_t)h*512*32 + b;
    float* o = out + (size_t)h*16384 + b;
    float lastO = 0.f, lastR = 0.f;

    #pragma unroll 1
    for (int sc = 0; sc < 32; ++sc){
        uint2 gv[16];
        #pragma unroll
        for (int j = 0; j < 16; ++j) gv[j] = gp[(size_t)(sc*16 + j)*32];
        float ov[16];
        #pragma unroll
        for (int j = 0; j < 16; ++j){
            float2 fi = __half22float2(*(const __half2*)&gv[j].x);
            float2 no = __half22float2(*(const __half2*)&gv[j].y);
            float F  = sigm(fi.x + hv.x);
            float I  = sigm(fi.y + hv.y);
            float Nc = tanh_f(no.x + hv.z);
            float O  = sigm(no.y + hv.w);
            c *= F;
            float r = c + Nc*I;
            ov[j] = tanh_f(r)*O;
            if (sc == 31 && j == 15){ lastO = ov[j]; lastR = r; }
        }
        #pragma unroll
        for (int j = 0; j < 16; ++j) o[(size_t)(sc*16 + j)*32] = ov[j];
    }
    out[(size_t)16777216 + b*Hh + h]          = lastO;
    out[(size_t)16777216 + 32768 + b*Hh + h]  = lastR;
}

// ================= launch =================
// Order puts gemm_kernel 4th so ncu (-s 5 -c 1, 2 harness launches first) profiles it.
extern "C" void kernel_launch(void* const* d_in, const int* in_sizes, int n_in,
                              void* d_out, int out_size) {
    (void)in_sizes; (void)n_in; (void)out_size;
    const float* inp = (const float*)d_in[0];
    const float* h0  = (const float*)d_in[1];
    const float* c0  = (const float*)d_in[2];
    const float* Uf  = (const float*)d_in[3];
    const float* Vf  = (const float*)d_in[4];
    const float* Bf  = (const float*)d_in[5];
    const float* Ui  = (const float*)d_in[6];
    const float* Vi  = (const float*)d_in[7];
    const float* Bi  = (const float*)d_in[8];
    const float* Ul  = (const float*)d_in[9];
    const float* Vl  = (const float*)d_in[10];
    const float* Bl  = (const float*)d_in[11];
    const float* Uu  = (const float*)d_in[12];
    const float* Vu  = (const float*)d_in[13];
    const float* Bu  = (const float*)d_in[14];
    float* out = (float*)d_out;

    cudaFuncSetAttribute(gemm_kernel,
                         cudaFuncAttributeMaxDynamicSharedMemorySize, GEMM_SMEM);

    pack_w_kernel<<<(Kk*Hh)/256, 256>>>(Uf, Ui, Ul, Uu);
    conv_inp_kernel<<<(Mm*(size_t)Kk/4)/256, 256>>>(inp);
    hv_part_kernel<<<128, 256>>>(h0, Vf, Vi, Vl, Vu);
    gemm_kernel<<<dim3(Nn/BN, Mm/BM), 128, GEMM_SMEM>>>();
    hv_reduce_kernel<<<128, 256>>>(Bf, Bi, Bl, Bu);
    phase2_kernel<<<256, 128>>>(c0, out);
}

// round 6
// speedup vs baseline: 1.2812x; 1.2812x over previous
#include <cuda_runtime.h>
#include <cuda_fp16.h>
#include <cstdint>

#define Bb 32
#define Ss 512
#define Dd 1024
#define Hh 1024
#define Mm (Bb*Ss)     // 16384, row order m' = s*32 + b
#define Nn 4096        // 4 gates * H, n = 4*h + g  (g: 0=f,1=i,2=l,3=u)
#define Kk 1024

// ---- scratch (device globals) ----
__device__ __half    g_A[(size_t)Mm*Kk];    // fp16 inp, rows m' = s*32+b
__device__ __half    g_W[(size_t)Kk*Nn];    // fp16 packed weights [k][4h+g]
__device__ uint32_t  g_FI[(size_t)Mm*1024]; // (F,I) fp16x2, index (h*512+s)*32+b
__device__ uint32_t  g_NO[(size_t)Mm*1024]; // (N,O) fp16x2, same index
__device__ float     g_hvT[1024*128];       // hvT[h][b*4+g]
__device__ float     g_hvp[8*32*4096];      // k-split partials [ks][b][g*1024+h]
__device__ float     g_qp[1024*4*32];       // quarter forget-products [h][q][b]

// ================= convert / pack =================
__global__ void conv_inp_kernel(const float* __restrict__ inp){
    size_t i = (size_t)blockIdx.x*blockDim.x + threadIdx.x;   // float4 index
    int row = (int)(i >> 8);
    int cb  = (int)(i & 255);
    int b = row >> 9, s = row & 511;
    int nrow = s*32 + b;
    float4 v = ((const float4*)inp)[i];
    __half2* dst = (__half2*)(g_A + (size_t)nrow*1024 + cb*4);
    dst[0] = __floats2half2_rn(v.x, v.y);
    dst[1] = __floats2half2_rn(v.z, v.w);
}

__global__ void pack_w_kernel(const float* __restrict__ Uf, const float* __restrict__ Ui,
                              const float* __restrict__ Ul, const float* __restrict__ Uu){
    int idx = blockIdx.x*blockDim.x + threadIdx.x;  // k*1024 + h
    int k = idx >> 10, h = idx & 1023;
    __half2 p0 = __floats2half2_rn(Uf[idx], Ui[idx]);
    __half2 p1 = __floats2half2_rn(Ul[idx], Uu[idx]);
    __half2* dst = (__half2*)(g_W + (size_t)k*Nn + 4*h);
    dst[0] = p0; dst[1] = p1;
}

// ================= hv: k-split partial GEMV =================
__global__ __launch_bounds__(256) void hv_part_kernel(const float* __restrict__ h0,
                          const float* __restrict__ Vf, const float* __restrict__ Vi,
                          const float* __restrict__ Vl, const float* __restrict__ Vu){
    const int ks = blockIdx.x & 7;
    const int gh = blockIdx.x >> 3;
    const int g  = gh >> 2, hc = gh & 3;
    const float* V = (g==0)?Vf:(g==1)?Vi:(g==2)?Vl:Vu;
    const int t = threadIdx.x;
    const int k0 = ks*128;
    __shared__ float s0[32][128];
    #pragma unroll
    for (int i = 0; i < 16; ++i){
        int idx = t + i*256;
        s0[idx >> 7][idx & 127] = h0[(idx >> 7)*1024 + k0 + (idx & 127)];
    }
    __syncthreads();
    const int h = hc*256 + t;
    float acc[32];
    #pragma unroll
    for (int b = 0; b < 32; ++b) acc[b] = 0.f;
    for (int k = 0; k < 128; ++k){
        float v = V[(size_t)(k0 + k)*1024 + h];
        #pragma unroll
        for (int b = 0; b < 32; ++b) acc[b] = fmaf(s0[b][k], v, acc[b]);
    }
    #pragma unroll
    for (int b = 0; b < 32; ++b)
        g_hvp[((size_t)ks*32 + b)*4096 + g*1024 + h] = acc[b];
}

__global__ __launch_bounds__(256) void hv_reduce_kernel(const float* __restrict__ Bf,
                          const float* __restrict__ Bi, const float* __restrict__ Bl,
                          const float* __restrict__ Bu){
    int idx = blockIdx.x*256 + threadIdx.x;   // 0..32767
    int b = idx >> 10, h = idx & 1023;
    float s0 = Bf[h], s1 = Bi[h], s2 = Bl[h], s3 = Bu[h];
    #pragma unroll
    for (int ks = 0; ks < 8; ++ks){
        const float* p = g_hvp + ((size_t)ks*32 + b)*4096;
        s0 += p[h]; s1 += p[1024 + h]; s2 += p[2048 + h]; s3 += p[3072 + h];
    }
    ((float4*)g_hvT)[h*32 + b] = make_float4(s0, s1, s2, s3);
}

// ================= GEMM: fp16 mma.sync, 4 warps 64x64, pipelined frags =================
#define BM 128
#define BN 128
#define BKk 64
#define APAD 72
#define BPAD 136
#define ABYTES (BM*APAD*2)      // 18432
#define BBYTES (BKk*BPAD*2)     // 17408
#define NSTAGE 3
#define GEMM_SMEM (NSTAGE*(ABYTES+BBYTES))   // 107520
#define NPITCH 132

__device__ __forceinline__ void cp16(uint32_t d, const void* s){
    asm volatile("cp.async.cg.shared.global [%0], [%1], 16;" :: "r"(d), "l"(s));
}
#define CP_COMMIT() asm volatile("cp.async.commit_group;")
#define CP_WAIT(n)  asm volatile("cp.async.wait_group %0;" :: "n"(n))

__device__ __forceinline__ void ldsm_x4(uint32_t& r0,uint32_t& r1,uint32_t& r2,uint32_t& r3,uint32_t a){
    asm volatile("ldmatrix.sync.aligned.m8n8.x4.shared.b16 {%0,%1,%2,%3},[%4];"
        : "=r"(r0),"=r"(r1),"=r"(r2),"=r"(r3) : "r"(a));
}
__device__ __forceinline__ void ldsm_x4t(uint32_t& r0,uint32_t& r1,uint32_t& r2,uint32_t& r3,uint32_t a){
    asm volatile("ldmatrix.sync.aligned.m8n8.x4.trans.shared.b16 {%0,%1,%2,%3},[%4];"
        : "=r"(r0),"=r"(r1),"=r"(r2),"=r"(r3) : "r"(a));
}
__device__ __forceinline__ void mma16816(float* c, const uint32_t* a, const uint32_t* b){
    asm volatile("mma.sync.aligned.m16n8k16.row.col.f32.f16.f16.f32 "
        "{%0,%1,%2,%3},{%4,%5,%6,%7},{%8,%9},{%0,%1,%2,%3};"
        : "+f"(c[0]),"+f"(c[1]),"+f"(c[2]),"+f"(c[3])
        : "r"(a[0]),"r"(a[1]),"r"(a[2]),"r"(a[3]),"r"(b[0]),"r"(b[1]));
}
__device__ __forceinline__ uint32_t smem_u32(const void* p){
    uint32_t a;
    asm("{ .reg .u64 t; cvta.to.shared.u64 t, %1; cvt.u32.u64 %0, t; }" : "=r"(a) : "l"(p));
    return a;
}

__global__ __launch_bounds__(128,2) void gemm_kernel(){
    extern __shared__ __align__(16) char smem[];
    const uint32_t sA = smem_u32(smem);
    const uint32_t sB = sA + NSTAGE*ABYTES;
    const int tid = threadIdx.x;
    const int lane = tid & 31, warp = tid >> 5;
    const int wm = warp >> 1, wn = warp & 1;          // 2x2 warps; warp tile 64x64
    const int m0 = blockIdx.y * BM, n0 = blockIdx.x * BN;

    float acc[4][8][4];
    #pragma unroll
    for (int i=0;i<4;i++)
        #pragma unroll
        for (int j=0;j<8;j++)
            #pragma unroll
            for (int r=0;r<4;r++) acc[i][j][r]=0.f;

    const __half* Ag = g_A + (size_t)m0*Kk;
    const __half* Wg = g_W + n0;

    // per-thread cp.async geometry
    const int arow0 = tid >> 3, ac0 = (tid & 7)*8;     // +i*16 rows
    const int brow0 = tid >> 4, bc0 = (tid & 15)*8;    // +i*8 rows

    auto issue_part = [&](int st, int buf, int part){
        const int k0 = st*BKk;
        #pragma unroll
        for (int i = part*2; i < part*2+2; ++i){
            int row = arow0 + i*16;
            cp16(sA + buf*ABYTES + (row*APAD + ac0)*2,
                 Ag + (size_t)row*Kk + k0 + ac0);
        }
        #pragma unroll
        for (int i = part*2; i < part*2+2; ++i){
            int row = brow0 + i*8;
            cp16(sB + buf*BBYTES + (row*BPAD + bc0)*2,
                 Wg + (size_t)(k0 + row)*Nn + bc0);
        }
    };
    auto issue_full = [&](int st, int buf){
        #pragma unroll
        for (int p = 0; p < 4; ++p) issue_part(st, buf, p);
    };

    const int arow = wm*64 + (lane & 15);
    const int acsel = (lane >> 4)*8;

    auto load_a = [&](int buf, int kk, uint32_t* a){
        const int acol = kk*16 + acsel;
        #pragma unroll
        for (int mt=0; mt<4; mt++)
            ldsm_x4(a[mt*4+0],a[mt*4+1],a[mt*4+2],a[mt*4+3],
                    sA + buf*ABYTES + (((arow + mt*16)*APAD) + acol)*2);
    };
    auto load_b = [&](int buf, int kk, uint32_t* bf){
        const int brow = kk*16 + (lane & 15);
        #pragma unroll
        for (int np=0; np<4; np++){
            const int bcol = wn*64 + np*16 + acsel;
            ldsm_x4t(bf[np*4+0],bf[np*4+1],bf[np*4+2],bf[np*4+3],
                     sB + buf*BBYTES + (brow*BPAD + bcol)*2);
        }
    };
    auto burst = [&](const uint32_t* a, const uint32_t* bf){
        #pragma unroll
        for (int mt=0; mt<4; mt++)
            #pragma unroll
            for (int nt=0; nt<8; nt++)
                mma16816(acc[mt][nt], a + mt*4, bf + (nt>>1)*4 + (nt&1)*2);
    };

    auto compute = [&](int buf, int stnext, int wbuf, bool do_issue){
        uint32_t aF[2][16], bF[2][16];
        load_a(buf, 0, aF[0]); load_b(buf, 0, bF[0]);
        #pragma unroll
        for (int kk = 0; kk < 4; ++kk){
            const int cur = kk & 1;
            if (kk < 3){ load_a(buf, kk+1, aF[cur^1]); load_b(buf, kk+1, bF[cur^1]); }
            if (do_issue) issue_part(stnext, wbuf, kk);
            burst(aF[cur], bF[cur]);
        }
    };

    issue_full(0,0); CP_COMMIT();
    issue_full(1,1); CP_COMMIT();

    const int NKT = Kk / BKk;   // 16
    int buf = 0;
    for (int kt = 0; kt < NKT-2; ++kt){
        CP_WAIT(1);
        __syncthreads();
        int wbuf = buf + 2; if (wbuf >= 3) wbuf -= 3;
        compute(buf, kt+2, wbuf, true);
        CP_COMMIT();
        if (++buf == 3) buf = 0;
    }
    CP_WAIT(1); __syncthreads(); compute(buf, 0, 0, false); if (++buf == 3) buf = 0;
    CP_WAIT(0); __syncthreads(); compute(buf, 0, 0, false);

    // ---- epilogue: smem transpose -> g_FI / g_NO (fp16x2, no hv) ----
    __syncthreads();
    float* sT = (float*)smem;   // 128 x NPITCH
    #pragma unroll
    for (int mt=0; mt<4; mt++){
        #pragma unroll
        for (int nt=0; nt<8; nt++){
            const int row = wm*64 + mt*16 + (lane >> 2);
            const int col = wn*64 + nt*8 + (lane & 3)*2;
            *(float2*)&sT[row*NPITCH + col]     = make_float2(acc[mt][nt][0], acc[mt][nt][1]);
            *(float2*)&sT[(row+8)*NPITCH + col] = make_float2(acc[mt][nt][2], acc[mt][nt][3]);
        }
    }
    __syncthreads();

    const int hbase = n0 >> 2;        // 32 h per CTA
    const int s0 = m0 >> 5;           // 4 s per CTA
    const int sl = lane >> 3, c8 = lane & 7;
    #pragma unroll
    for (int hb = 0; hb < 8; ++hb){
        const int hl = hb*4 + warp;
        const int hglob = hbase + hl;
        const int s = s0 + sl;
        uint32_t fiU[4], noU[4];
        #pragma unroll
        for (int db = 0; db < 4; ++db){
            const int b = 4*c8 + db;
            float4 v = *(const float4*)&sT[(sl*32 + b)*NPITCH + hl*4];
            __half2 fi = __floats2half2_rn(v.x, v.y);
            __half2 no = __floats2half2_rn(v.z, v.w);
            fiU[db] = *(uint32_t*)&fi;
            noU[db] = *(uint32_t*)&no;
        }
        size_t base = ((size_t)hglob*512 + s)*32 + 4*c8;
        *(uint4*)&g_FI[base] = make_uint4(fiU[0], fiU[1], fiU[2], fiU[3]);
        *(uint4*)&g_NO[base] = make_uint4(noU[0], noU[1], noU[2], noU[3]);
    }
}

// ================= activations =================
__device__ __forceinline__ float tanha(float x){
    float y; asm("tanh.approx.f32 %0, %1;" : "=f"(y) : "f"(x)); return y;
}
__device__ __forceinline__ float sigm(float x){
    return fmaf(0.5f, tanha(0.5f*x), 0.5f);
}

// ================= phase A: quarter forget-products =================
// grid 1024 (h), block 128: warp = quarter q, lane = b
__global__ __launch_bounds__(128) void qprod_kernel(){
    const int h = blockIdx.x;
    const int q = threadIdx.x >> 5, b = threadIdx.x & 31;
    const float hvF = g_hvT[h*128 + b*4];
    const uint32_t* p = g_FI + ((size_t)h*512 + q*128)*32 + b;
    float prod = 1.f;
    #pragma unroll 1
    for (int jc = 0; jc < 8; ++jc){
        uint32_t u[16];
        #pragma unroll
        for (int j = 0; j < 16; ++j) u[j] = p[(size_t)(jc*16 + j)*32];
        #pragma unroll
        for (int j = 0; j < 16; ++j){
            float f = __half22float2(*(const __half2*)&u[j]).x;
            prod *= sigm(f + hvF);
        }
    }
    g_qp[(h*4 + q)*32 + b] = prod;
}

// ================= phase B: outputs with carry =================
// grid 1024 (h), block 128: warp = quarter q, lane = b
__global__ __launch_bounds__(128) void phase2_kernel(const float* __restrict__ c0,
                                                     float* __restrict__ out){
    const int h = blockIdx.x;
    const int q = threadIdx.x >> 5, b = threadIdx.x & 31;
    float4 hv = ((const float4*)g_hvT)[h*32 + b];   // (F, I, N, O)
    float c = c0[b*Hh + h];
    #pragma unroll
    for (int qq = 0; qq < 3; ++qq)
        if (qq < q) c *= g_qp[(h*4 + qq)*32 + b];

    const size_t base = ((size_t)h*512 + q*128)*32 + b;
    const uint32_t* pFI = g_FI + base;
    const uint32_t* pNO = g_NO + base;
    float* o = out + (size_t)h*16384 + q*128*32 + b;
    float lastO = 0.f, lastR = 0.f;

    #pragma unroll 1
    for (int jc = 0; jc < 8; ++jc){
        uint32_t ufi[16], uno[16];
        #pragma unroll
        for (int j = 0; j < 16; ++j){
            ufi[j] = pFI[(size_t)(jc*16 + j)*32];
            uno[j] = pNO[(size_t)(jc*16 + j)*32];
        }
        float ov[16];
        #pragma unroll
        for (int j = 0; j < 16; ++j){
            float2 fi = __half22float2(*(const __half2*)&ufi[j]);
            float2 no = __half22float2(*(const __half2*)&uno[j]);
            float F  = sigm(fi.x + hv.x);
            float I  = sigm(fi.y + hv.y);
            float Nc = tanha(no.x + hv.z);
            float O  = sigm(no.y + hv.w);
            c *= F;
            float r = c + Nc*I;
            ov[j] = tanha(r)*O;
            if (jc == 7 && j == 15){ lastO = ov[j]; lastR = r; }
        }
        #pragma unroll
        for (int j = 0; j < 16; ++j) o[(size_t)(jc*16 + j)*32] = ov[j];
    }
    if (q == 3){
        out[(size_t)16777216 + b*Hh + h]          = lastO;
        out[(size_t)16777216 + 32768 + b*Hh + h]  = lastR;
    }
}

// ================= launch =================
// gemm_kernel is the 4th user launch so ncu (-s 5 -c 1) profiles it.
extern "C" void kernel_launch(void* const* d_in, const int* in_sizes, int n_in,
                              void* d_out, int out_size) {
    (void)in_sizes; (void)n_in; (void)out_size;
    const float* inp = (const float*)d_in[0];
    const float* h0  = (const float*)d_in[1];
    const float* c0  = (const float*)d_in[2];
    const float* Uf  = (const float*)d_in[3];
    const float* Vf  = (const float*)d_in[4];
    const float* Bf  = (const float*)d_in[5];
    const float* Ui  = (const float*)d_in[6];
    const float* Vi  = (const float*)d_in[7];
    const float* Bi  = (const float*)d_in[8];
    const float* Ul  = (const float*)d_in[9];
    const float* Vl  = (const float*)d_in[10];
    const float* Bl  = (const float*)d_in[11];
    const float* Uu  = (const float*)d_in[12];
    const float* Vu  = (const float*)d_in[13];
    const float* Bu  = (const float*)d_in[14];
    float* out = (float*)d_out;

    cudaFuncSetAttribute(gemm_kernel,
                         cudaFuncAttributeMaxDynamicSharedMemorySize, GEMM_SMEM);

    pack_w_kernel<<<(Kk*Hh)/256, 256>>>(Uf, Ui, Ul, Uu);
    conv_inp_kernel<<<(Mm*(size_t)Kk/4)/256, 256>>>(inp);
    hv_part_kernel<<<128, 256>>>(h0, Vf, Vi, Vl, Vu);
    gemm_kernel<<<dim3(Nn/BN, Mm/BM), 128, GEMM_SMEM>>>();
    hv_reduce_kernel<<<128, 256>>>(Bf, Bi, Bl, Bu);
    qprod_kernel<<<1024, 128>>>();
    phase2_kernel<<<1024, 128>>>(c0, out);
}